// round 12
// baseline (speedup 1.0000x reference)
#include <cuda_runtime.h>
#include <cstdint>

#define BB 8
#define NN 1024
#define HH 512

// Scratch (allocation-free rule: __device__ globals)
__device__ float g_act[(size_t)BB * NN * 4 * HH];   // 8192 x 2048 : [U | Q | K | V]
__device__ float g_attn[(size_t)BB * NN * HH];      // 8192 x 512 (gated, tf32-rounded)
__device__ float g_ts[BB * NN];                     // timestamps fp32 (seconds)
__device__ float g_xr[(size_t)BB * NN * HH];        // x rounded to tf32
__device__ float g_w1r[(size_t)4 * HH * HH];        // f1_w rounded to tf32
__device__ float g_w2r[(size_t)HH * HH];            // f2_w rounded to tf32
__device__ float g_bias[(size_t)BB * NN * NN];      // rel-attn bias (head-independent)

// ---------------------------------------------------------------------------
__device__ __forceinline__ uint32_t smem_u32(const void* p) {
    uint32_t a;
    asm("{ .reg .u64 t; cvta.to.shared.u64 t, %1; cvt.u32.u64 %0, t; }" : "=r"(a) : "l"(p));
    return a;
}
__device__ __forceinline__ float to_tf32(float x) {
    float r; asm("cvt.rna.tf32.f32 %0, %1;" : "=f"(r) : "f"(x)); return r;
}

#define CP_ASYNC16(dst, src) \
    asm volatile("cp.async.cg.shared.global [%0], [%1], 16;" :: "r"(dst), "l"(src) : "memory")
#define CP_COMMIT() asm volatile("cp.async.commit_group;" ::: "memory")
#define CP_WAIT1()  asm volatile("cp.async.wait_group 1;" ::: "memory")
#define CP_WAIT0()  asm volatile("cp.async.wait_group 0;" ::: "memory")

#define MMA_TF32(c, a, b)                                                        \
    asm volatile("mma.sync.aligned.m16n8k8.row.col.f32.tf32.tf32.f32 "           \
        "{%0,%1,%2,%3}, {%4,%5,%6,%7}, {%8,%9}, {%0,%1,%2,%3};"                  \
        : "+f"((c)[0]), "+f"((c)[1]), "+f"((c)[2]), "+f"((c)[3])                  \
        : "r"((a)[0]), "r"((a)[1]), "r"((a)[2]), "r"((a)[3]),                     \
          "r"((b)[0]), "r"((b)[1]))

// ---------------------------------------------------------------------------
// Prep kernels
// ---------------------------------------------------------------------------
__global__ void ts_convert_kernel(const int* __restrict__ t, float* __restrict__ out) {
    bool is64 = (t[1] == 0 && t[3] == 0 && t[5] == 0 && t[7] == 0);
    int i = blockIdx.x * blockDim.x + threadIdx.x;
    if (i < BB * NN) {
        long long v = is64 ? ((const long long*)t)[i] : (long long)t[i];
        float tv = (float)v;
        out[i] = tv / 1e9f;
    }
}

__global__ void round_tf32_kernel(const float* __restrict__ in, float* __restrict__ out, int n) {
    int i = blockIdx.x * blockDim.x + threadIdx.x;
    if (i < n) out[i] = to_tf32(in[i]);
}

// Precompute bias[b][q][k] = pos_w[N-1+k-q] + ts_w[bucket(|ts_ext[q+1]-ts[k]|)]
__global__ __launch_bounds__(256) void bias_kernel(
    const float* __restrict__ ts, const float* __restrict__ ts_w,
    const float* __restrict__ pos_w, float* __restrict__ bias)
{
    int b = blockIdx.y;
    int idx = blockIdx.x;
    int qt = (int)((sqrtf(8.f * idx + 1.f) - 1.f) * 0.5f);
    while ((qt + 1) * (qt + 2) / 2 <= idx) qt++;
    while (qt * (qt + 1) / 2 > idx) qt--;
    int kt = idx - qt * (qt + 1) / 2;
    int q0 = qt * 64, k0 = kt * 64;
    const float* tsb = ts + b * NN;
    int tid = threadIdx.x;

    #pragma unroll
    for (int it = 0; it < 4; it++) {
        int r = (tid >> 4) + it * 16;
        int c = (tid & 15) * 4;
        int q = q0 + r;
        float tq = tsb[min(q + 1, NN - 1)];
        float4 o;
        #pragma unroll
        for (int j = 0; j < 4; j++) {
            int k = k0 + c + j;
            float ad = fmaxf(fabsf(tq - tsb[k]), 1.0f);
            int bucket = (int)floorf(__logf(ad) * 3.3222591f);
            bucket = bucket < 0 ? 0 : (bucket > 64 ? 64 : bucket);
            ((float*)&o)[j] = pos_w[NN - 1 + k - q] + ts_w[bucket];
        }
        *(float4*)(bias + ((size_t)(b * NN + q)) * NN + k0 + c) = o;
    }
}

// ---------------------------------------------------------------------------
// mma.sync tf32 GEMM: C = A*W^T + bias (opt SiLU)
// CTA 128x128, 128 threads (4 warps 2x2), warp tile 64x64, 2 CTAs/SM.
// THREE smem stages, prefetch distance 2, SINGLE barrier per stage:
// the buffer written at iter s ((s+2)%3) was last read at iter s-1, and the
// top-of-iter barrier (required for cp.async visibility anyway) proves all
// warps finished those reads. Loads are issued BEFORE the MMA block so the
// L2 round trip overlaps tensor work.
// ---------------------------------------------------------------------------
#define GK 512
#define LDS_K 36
#define A_BYTES (128 * LDS_K * 4)
#define B_BYTES (128 * LDS_K * 4)
#define STAGE_BYTES (A_BYTES + B_BYTES)       // 36864
#define GEMM_SMEM (3 * STAGE_BYTES)           // 110592

template<bool SILU>
__global__ __launch_bounds__(128, 2) void gemm_mma_kernel(
    const float* __restrict__ A, const float* __restrict__ W,
    const float* __restrict__ bias, float* __restrict__ C, int ldc)
{
    extern __shared__ char smem[];
    const uint32_t sb = smem_u32(smem);
    const int tid = threadIdx.x;
    const int lane = tid & 31;
    const int wid = tid >> 5;          // 0..3
    const int wm = wid >> 1;           // 0..1
    const int wn = wid & 1;            // 0..1
    const int l4 = lane >> 2;
    const int lc = lane & 3;
    const int m0 = blockIdx.y * 128;
    const int n0 = blockIdx.x * 128;

    auto load_stage = [&](int s, int buf) {
        uint32_t base = sb + buf * STAGE_BYTES;
        const float* a0 = A + (size_t)m0 * GK + s * 32;
        #pragma unroll
        for (int q = 0; q < 8; q++) {          // 128 rows x 8 segs / 128 thr
            int idx = q * 128 + tid;
            int r = idx >> 3, c = idx & 7;
            CP_ASYNC16(base + r * (LDS_K * 4) + c * 16, a0 + (size_t)r * GK + c * 4);
        }
        const float* b0 = W + (size_t)n0 * GK + s * 32;
        #pragma unroll
        for (int q = 0; q < 8; q++) {
            int idx = q * 128 + tid;
            int r = idx >> 3, c = idx & 7;
            CP_ASYNC16(base + A_BYTES + r * (LDS_K * 4) + c * 16, b0 + (size_t)r * GK + c * 4);
        }
    };

    load_stage(0, 0); CP_COMMIT();
    load_stage(1, 1); CP_COMMIT();

    float acc[4][8][4];
    #pragma unroll
    for (int mt = 0; mt < 4; mt++)
        #pragma unroll
        for (int nt = 0; nt < 8; nt++)
            #pragma unroll
            for (int i = 0; i < 4; i++) acc[mt][nt][i] = 0.f;

    const int NSTAGE = GK / 32;   // 16
    #pragma unroll 1
    for (int s = 0; s < NSTAGE; s++) {
        if (s + 1 < NSTAGE) { CP_WAIT1(); } else { CP_WAIT0(); }
        __syncthreads();   // the ONLY barrier per stage

        // issue next loads first — overlap L2 latency with the MMA burst
        if (s + 2 < NSTAGE) { load_stage(s + 2, (s + 2) % 3); CP_COMMIT(); }

        const int buf = s % 3;
        const float* As = (const float*)(smem + buf * STAGE_BYTES);
        const float* Bs = (const float*)(smem + buf * STAGE_BYTES + A_BYTES);
        const int arow = wm * 64 + l4;
        const int brow = wn * 64 + l4;

        #pragma unroll
        for (int kk = 0; kk < 4; kk++) {
            int kA = kk * 8 + lc;
            uint32_t a[4][4], b[8][2];
            #pragma unroll
            for (int mt = 0; mt < 4; mt++) {
                const float* p = As + (arow + mt * 16) * LDS_K + kA;
                a[mt][0] = __float_as_uint(p[0]);
                a[mt][1] = __float_as_uint(p[8 * LDS_K]);
                a[mt][2] = __float_as_uint(p[4]);
                a[mt][3] = __float_as_uint(p[8 * LDS_K + 4]);
            }
            #pragma unroll
            for (int nt = 0; nt < 8; nt++) {
                const float* p = Bs + (brow + nt * 8) * LDS_K + kA;
                b[nt][0] = __float_as_uint(p[0]);
                b[nt][1] = __float_as_uint(p[4]);
            }
            #pragma unroll
            for (int mt = 0; mt < 4; mt++)
                #pragma unroll
                for (int nt = 0; nt < 8; nt++)
                    MMA_TF32(acc[mt][nt], a[mt], b[nt]);
        }
    }

    #pragma unroll
    for (int mt = 0; mt < 4; mt++) {
        int r0 = m0 + wm * 64 + mt * 16 + l4;
        #pragma unroll
        for (int nt = 0; nt < 8; nt++) {
            int c0 = n0 + wn * 64 + nt * 8 + 2 * lc;
            float bv0 = bias[c0], bv1 = bias[c0 + 1];
            float v0 = acc[mt][nt][0] + bv0;
            float v1 = acc[mt][nt][1] + bv1;
            float v2 = acc[mt][nt][2] + bv0;
            float v3 = acc[mt][nt][3] + bv1;
            if (SILU) {
                v0 = __fdividef(v0, 1.f + __expf(-v0));
                v1 = __fdividef(v1, 1.f + __expf(-v1));
                v2 = __fdividef(v2, 1.f + __expf(-v2));
                v3 = __fdividef(v3, 1.f + __expf(-v3));
            }
            *(float2*)(C + (size_t)r0 * ldc + c0) = make_float2(v0, v1);
            *(float2*)(C + (size_t)(r0 + 8) * ldc + c0) = make_float2(v2, v3);
        }
    }
}

// ---------------------------------------------------------------------------
// Tensor-core attention (128 threads, 4 warps) with precomputed bias.
// S-phase: warp w covers keys [w*16, w*16+16). PV: d-cols [w*16, w*16+16).
// ---------------------------------------------------------------------------
#define PQK 68
#define PV2 72
#define PS  72
#define ATTN_SMEM ((64 * PQK * 2 + 64 * PV2 + 64 * PS) * 4)

__global__ __launch_bounds__(128) void attn_tc_kernel(
    const float* __restrict__ act,
    const float* __restrict__ bias,
    float* __restrict__ attn_out)
{
    extern __shared__ float sm[];
    float* Qs = sm;                     // 64 x 68
    float* Ks = Qs + 64 * PQK;          // 64 x 68
    float* Vs = Ks + 64 * PQK;          // 64 x 72 ([key][d])
    float* Ss = Vs + 64 * PV2;          // 64 x 72 (bias in / weights out)
    const uint32_t ss_base = smem_u32(Ss);

    const int tid = threadIdx.x;
    const int lane = tid & 31;
    const int w = tid >> 5;
    const int l4 = lane >> 2;
    const int lc = lane & 3;
    const int qt = 15 - blockIdx.x;     // heavy tiles first
    const int bh = blockIdx.y;
    const int b = bh >> 3, h = bh & 7;
    const int q0 = qt * 64;

    const float* actb = act + (size_t)b * NN * 2048;

    // Q tile: prescale by 0.125 (exact), round to tf32
    for (int i = tid; i < 64 * 16; i += 128) {
        int r = i >> 4, c4 = (i & 15) * 4;
        float4 v = *(const float4*)(actb + (size_t)(q0 + r) * 2048 + 512 + h * 64 + c4);
        Qs[r * PQK + c4 + 0] = to_tf32(v.x * 0.125f);
        Qs[r * PQK + c4 + 1] = to_tf32(v.y * 0.125f);
        Qs[r * PQK + c4 + 2] = to_tf32(v.z * 0.125f);
        Qs[r * PQK + c4 + 3] = to_tf32(v.w * 0.125f);
    }

    float acc[4][2][4];
    #pragma unroll
    for (int mt = 0; mt < 4; mt++)
        #pragma unroll
        for (int nt = 0; nt < 2; nt++)
            #pragma unroll
            for (int j = 0; j < 4; j++) acc[mt][nt][j] = 0.f;

    #pragma unroll 1
    for (int kt = 0; kt <= qt; kt++) {
        const int k0 = kt * 64;
        __syncthreads();   // prev-iter readers of Ss/Ks/Vs done

        // bias tile -> Ss via cp.async (overlaps with K/V LDG below)
        const float* bsrc = bias + ((size_t)(b * NN + q0)) * NN + k0;
        #pragma unroll
        for (int q8 = 0; q8 < 8; q8++) {
            int idx = q8 * 128 + tid;
            int r = idx >> 4, c = idx & 15;
            CP_ASYNC16(ss_base + (r * PS + c * 4) * 4, bsrc + (size_t)r * NN + c * 4);
        }
        CP_COMMIT();

        // K / V tiles (tf32-rounded)
        for (int i = tid; i < 64 * 16; i += 128) {
            int r = i >> 4, c4 = (i & 15) * 4;
            float4 kv = *(const float4*)(actb + (size_t)(k0 + r) * 2048 + 1024 + h * 64 + c4);
            Ks[r * PQK + c4 + 0] = to_tf32(kv.x);
            Ks[r * PQK + c4 + 1] = to_tf32(kv.y);
            Ks[r * PQK + c4 + 2] = to_tf32(kv.z);
            Ks[r * PQK + c4 + 3] = to_tf32(kv.w);
            float4 vv = *(const float4*)(actb + (size_t)(k0 + r) * 2048 + 1536 + h * 64 + c4);
            Vs[r * PV2 + c4 + 0] = to_tf32(vv.x);
            Vs[r * PV2 + c4 + 1] = to_tf32(vv.y);
            Vs[r * PV2 + c4 + 2] = to_tf32(vv.z);
            Vs[r * PV2 + c4 + 3] = to_tf32(vv.w);
        }
        CP_WAIT0();
        __syncthreads();

        // --- S = (Q*scale) K^T (warp w covers keys [w*16, w*16+16)) ---
        float sacc[4][2][4];
        #pragma unroll
        for (int mt = 0; mt < 4; mt++)
            #pragma unroll
            for (int nt = 0; nt < 2; nt++)
                #pragma unroll
                for (int j = 0; j < 4; j++) sacc[mt][nt][j] = 0.f;

        #pragma unroll
        for (int ks = 0; ks < 8; ks++) {
            int kA = ks * 8 + lc;
            uint32_t a[4][4], bb[2][2];
            #pragma unroll
            for (int mt = 0; mt < 4; mt++) {
                const float* p = Qs + (mt * 16 + l4) * PQK + kA;
                a[mt][0] = __float_as_uint(p[0]);
                a[mt][1] = __float_as_uint(p[8 * PQK]);
                a[mt][2] = __float_as_uint(p[4]);
                a[mt][3] = __float_as_uint(p[8 * PQK + 4]);
            }
            #pragma unroll
            for (int nt = 0; nt < 2; nt++) {
                const float* p = Ks + (w * 16 + nt * 8 + l4) * PQK + kA;
                bb[nt][0] = __float_as_uint(p[0]);
                bb[nt][1] = __float_as_uint(p[4]);
            }
            #pragma unroll
            for (int mt = 0; mt < 4; mt++)
                #pragma unroll
                for (int nt = 0; nt < 2; nt++)
                    MMA_TF32(sacc[mt][nt], a[mt], bb[nt]);
        }

        // --- epilogue: score + bias -> silu -> mask; RMW Ss in-place ---
        const bool diag = (kt == qt);
        #pragma unroll
        for (int mt = 0; mt < 4; mt++) {
            #pragma unroll
            for (int nt = 0; nt < 2; nt++) {
                int kl = w * 16 + nt * 8 + 2 * lc;
                #pragma unroll
                for (int half = 0; half < 2; half++) {
                    int ql = mt * 16 + l4 + half * 8;
                    float2 bv = *(const float2*)&Ss[ql * PS + kl];
                    float sc0 = sacc[mt][nt][half * 2 + 0] + bv.x;
                    float sc1 = sacc[mt][nt][half * 2 + 1] + bv.y;
                    float v0 = __fdividef(sc0, 1.f + __expf(-sc0));
                    float v1 = __fdividef(sc1, 1.f + __expf(-sc1));
                    if (diag) {
                        if (kl > ql) v0 = 0.f;
                        if (kl + 1 > ql) v1 = 0.f;
                    }
                    float2 o; o.x = to_tf32(v0); o.y = to_tf32(v1);
                    *(float2*)&Ss[ql * PS + kl] = o;
                }
            }
        }
        __syncthreads();

        // --- PV: acc += S @ V (warp w covers d-cols [w*16, w*16+16)) ---
        #pragma unroll
        for (int ks = 0; ks < 8; ks++) {
            int kA = ks * 8 + lc;
            uint32_t a[4][4], bb[2][2];
            #pragma unroll
            for (int mt = 0; mt < 4; mt++) {
                const float* p = Ss + (mt * 16 + l4) * PS + kA;
                a[mt][0] = __float_as_uint(p[0]);
                a[mt][1] = __float_as_uint(p[8 * PS]);
                a[mt][2] = __float_as_uint(p[4]);
                a[mt][3] = __float_as_uint(p[8 * PS + 4]);
            }
            #pragma unroll
            for (int nt = 0; nt < 2; nt++) {
                const float* p = Vs + (ks * 8 + lc) * PV2 + w * 16 + nt * 8 + l4;
                bb[nt][0] = __float_as_uint(p[0]);
                bb[nt][1] = __float_as_uint(p[4 * PV2]);
            }
            #pragma unroll
            for (int mt = 0; mt < 4; mt++)
                #pragma unroll
                for (int nt = 0; nt < 2; nt++)
                    MMA_TF32(acc[mt][nt], a[mt], bb[nt]);
        }
    }

    // --- output: gate by U, round to tf32 for GEMM2 ---
    #pragma unroll
    for (int mt = 0; mt < 4; mt++) {
        #pragma unroll
        for (int half = 0; half < 2; half++) {
            int q = q0 + mt * 16 + l4 + half * 8;
            #pragma unroll
            for (int nt = 0; nt < 2; nt++) {
                int d = w * 16 + nt * 8 + 2 * lc;
                float2 uv = *(const float2*)(actb + (size_t)q * 2048 + h * 64 + d);
                float2 o;
                o.x = to_tf32(acc[mt][nt][half * 2 + 0] * uv.x);
                o.y = to_tf32(acc[mt][nt][half * 2 + 1] * uv.y);
                *(float2*)(attn_out + ((size_t)b * NN + q) * HH + h * 64 + d) = o;
            }
        }
    }
}

// ---------------------------------------------------------------------------
extern "C" void kernel_launch(void* const* d_in, const int* in_sizes, int n_in,
                              void* d_out, int out_size) {
    const float* x     = (const float*)d_in[0];
    const int*   tsi   = (const int*)  d_in[1];
    const float* f1_w  = (const float*)d_in[3];
    const float* f1_b  = (const float*)d_in[4];
    const float* f2_w  = (const float*)d_in[5];
    const float* f2_b  = (const float*)d_in[6];
    const float* ts_w  = (const float*)d_in[7];
    const float* pos_w = (const float*)d_in[8];
    float* out = (float*)d_out;

    float *actp, *attnp, *tsp, *xrp, *w1p, *w2p, *biasp;
    cudaGetSymbolAddress((void**)&actp, g_act);
    cudaGetSymbolAddress((void**)&attnp, g_attn);
    cudaGetSymbolAddress((void**)&tsp, g_ts);
    cudaGetSymbolAddress((void**)&xrp, g_xr);
    cudaGetSymbolAddress((void**)&w1p, g_w1r);
    cudaGetSymbolAddress((void**)&w2p, g_w2r);
    cudaGetSymbolAddress((void**)&biasp, g_bias);

    cudaFuncSetAttribute(gemm_mma_kernel<true>,
                         cudaFuncAttributeMaxDynamicSharedMemorySize, GEMM_SMEM);
    cudaFuncSetAttribute(gemm_mma_kernel<false>,
                         cudaFuncAttributeMaxDynamicSharedMemorySize, GEMM_SMEM);
    cudaFuncSetAttribute(attn_tc_kernel,
                         cudaFuncAttributeMaxDynamicSharedMemorySize, ATTN_SMEM);

    // Launch order keeps GEMM1 at index 3 (the slot ncu samples).
    ts_convert_kernel<<<32, 256>>>(tsi, tsp);                                     // 0
    round_tf32_kernel<<<(BB * NN * HH + 255) / 256, 256>>>(x, xrp, BB * NN * HH); // 1
    round_tf32_kernel<<<(4 * HH * HH + 255) / 256, 256>>>(f1_w, w1p, 4 * HH * HH);// 2

    // 3: GEMM1 + SiLU (profiled slot): [8192,512] @ [2048,512]^T
    gemm_mma_kernel<true><<<dim3(16, 64), 128, GEMM_SMEM>>>(xrp, w1p, f1_b, actp, 4 * HH);

    round_tf32_kernel<<<(HH * HH + 255) / 256, 256>>>(f2_w, w2p, HH * HH);        // 4
    bias_kernel<<<dim3(136, BB), 256>>>(tsp, ts_w, pos_w, biasp);                 // 5

    // 6: tensor-core attention (+ fused U gating, tf32 round)
    attn_tc_kernel<<<dim3(16, 64), 128, ATTN_SMEM>>>(actp, biasp, attnp);

    // 7: GEMM2: gated @ [512,512]^T + f2_b -> out
    gemm_mma_kernel<false><<<dim3(4, 64), 128, GEMM_SMEM>>>(attnp, w2p, f2_b, out, HH);
}

// round 14
// speedup vs baseline: 1.0041x; 1.0041x over previous
#include <cuda_runtime.h>
#include <cstdint>

#define BB 8
#define NN 1024
#define HH 512

// Scratch (allocation-free rule: __device__ globals)
__device__ float g_act[(size_t)BB * NN * 4 * HH];   // 8192 x 2048 : [U | Q | K | V]
__device__ float g_attn[(size_t)BB * NN * HH];      // 8192 x 512 (gated, tf32-rounded)
__device__ float g_ts[BB * NN];                     // timestamps fp32 (seconds)
__device__ float g_xr[(size_t)BB * NN * HH];        // x rounded to tf32
__device__ float g_w1r[(size_t)4 * HH * HH];        // f1_w rounded to tf32
__device__ float g_w2r[(size_t)HH * HH];            // f2_w rounded to tf32
__device__ float g_bias[(size_t)BB * NN * NN];      // rel-attn bias (head-independent)

// ---------------------------------------------------------------------------
__device__ __forceinline__ uint32_t smem_u32(const void* p) {
    uint32_t a;
    asm("{ .reg .u64 t; cvta.to.shared.u64 t, %1; cvt.u32.u64 %0, t; }" : "=r"(a) : "l"(p));
    return a;
}
__device__ __forceinline__ float to_tf32(float x) {
    float r; asm("cvt.rna.tf32.f32 %0, %1;" : "=f"(r) : "f"(x)); return r;
}

#define CP_ASYNC16(dst, src) \
    asm volatile("cp.async.cg.shared.global [%0], [%1], 16;" :: "r"(dst), "l"(src) : "memory")
#define CP_COMMIT() asm volatile("cp.async.commit_group;" ::: "memory")
#define CP_WAIT1()  asm volatile("cp.async.wait_group 1;" ::: "memory")
#define CP_WAIT0()  asm volatile("cp.async.wait_group 0;" ::: "memory")

#define MMA_TF32(c, a, b)                                                        \
    asm volatile("mma.sync.aligned.m16n8k8.row.col.f32.tf32.tf32.f32 "           \
        "{%0,%1,%2,%3}, {%4,%5,%6,%7}, {%8,%9}, {%0,%1,%2,%3};"                  \
        : "+f"((c)[0]), "+f"((c)[1]), "+f"((c)[2]), "+f"((c)[3])                  \
        : "r"((a)[0]), "r"((a)[1]), "r"((a)[2]), "r"((a)[3]),                     \
          "r"((b)[0]), "r"((b)[1]))

// ---------------------------------------------------------------------------
// Prep kernels
// ---------------------------------------------------------------------------
__global__ void ts_convert_kernel(const int* __restrict__ t, float* __restrict__ out) {
    bool is64 = (t[1] == 0 && t[3] == 0 && t[5] == 0 && t[7] == 0);
    int i = blockIdx.x * blockDim.x + threadIdx.x;
    if (i < BB * NN) {
        long long v = is64 ? ((const long long*)t)[i] : (long long)t[i];
        float tv = (float)v;
        out[i] = tv / 1e9f;
    }
}

__global__ void round_tf32_kernel(const float* __restrict__ in, float* __restrict__ out, int n) {
    int i = blockIdx.x * blockDim.x + threadIdx.x;
    if (i < n) out[i] = to_tf32(in[i]);
}

// Precompute bias[b][q][k] = pos_w[N-1+k-q] + ts_w[bucket(|ts_ext[q+1]-ts[k]|)]
__global__ __launch_bounds__(256) void bias_kernel(
    const float* __restrict__ ts, const float* __restrict__ ts_w,
    const float* __restrict__ pos_w, float* __restrict__ bias)
{
    int b = blockIdx.y;
    int idx = blockIdx.x;
    int qt = (int)((sqrtf(8.f * idx + 1.f) - 1.f) * 0.5f);
    while ((qt + 1) * (qt + 2) / 2 <= idx) qt++;
    while (qt * (qt + 1) / 2 > idx) qt--;
    int kt = idx - qt * (qt + 1) / 2;
    int q0 = qt * 64, k0 = kt * 64;
    const float* tsb = ts + b * NN;
    int tid = threadIdx.x;

    #pragma unroll
    for (int it = 0; it < 4; it++) {
        int r = (tid >> 4) + it * 16;
        int c = (tid & 15) * 4;
        int q = q0 + r;
        float tq = tsb[min(q + 1, NN - 1)];
        float4 o;
        #pragma unroll
        for (int j = 0; j < 4; j++) {
            int k = k0 + c + j;
            float ad = fmaxf(fabsf(tq - tsb[k]), 1.0f);
            int bucket = (int)floorf(__logf(ad) * 3.3222591f);
            bucket = bucket < 0 ? 0 : (bucket > 64 ? 64 : bucket);
            ((float*)&o)[j] = pos_w[NN - 1 + k - q] + ts_w[bucket];
        }
        *(float4*)(bias + ((size_t)(b * NN + q)) * NN + k0 + c) = o;
    }
}

// ---------------------------------------------------------------------------
// mma.sync tf32 GEMM: C = A*W^T + bias (opt SiLU)
// CTA 128x128, 128 threads (4 warps 2x2), warp tile 64x64, 2 CTAs/SM.
// THREE smem stages, prefetch distance 2, SINGLE barrier per stage:
// the buffer written at iter s ((s+2)%3) was last read at iter s-1, and the
// top-of-iter barrier (required for cp.async visibility anyway) proves all
// warps finished those reads. Loads are issued BEFORE the MMA block so the
// L2 round trip overlaps tensor work.
// ---------------------------------------------------------------------------
#define GK 512
#define LDS_K 36
#define A_BYTES (128 * LDS_K * 4)
#define B_BYTES (128 * LDS_K * 4)
#define STAGE_BYTES (A_BYTES + B_BYTES)       // 36864
#define GEMM_SMEM (3 * STAGE_BYTES)           // 110592

template<bool SILU>
__global__ __launch_bounds__(128, 2) void gemm_mma_kernel(
    const float* __restrict__ A, const float* __restrict__ W,
    const float* __restrict__ bias, float* __restrict__ C, int ldc)
{
    extern __shared__ char smem[];
    const uint32_t sb = smem_u32(smem);
    const int tid = threadIdx.x;
    const int lane = tid & 31;
    const int wid = tid >> 5;          // 0..3
    const int wm = wid >> 1;           // 0..1
    const int wn = wid & 1;            // 0..1
    const int l4 = lane >> 2;
    const int lc = lane & 3;
    const int m0 = blockIdx.y * 128;
    const int n0 = blockIdx.x * 128;

    auto load_stage = [&](int s, int buf) {
        uint32_t base = sb + buf * STAGE_BYTES;
        const float* a0 = A + (size_t)m0 * GK + s * 32;
        #pragma unroll
        for (int q = 0; q < 8; q++) {          // 128 rows x 8 segs / 128 thr
            int idx = q * 128 + tid;
            int r = idx >> 3, c = idx & 7;
            CP_ASYNC16(base + r * (LDS_K * 4) + c * 16, a0 + (size_t)r * GK + c * 4);
        }
        const float* b0 = W + (size_t)n0 * GK + s * 32;
        #pragma unroll
        for (int q = 0; q < 8; q++) {
            int idx = q * 128 + tid;
            int r = idx >> 3, c = idx & 7;
            CP_ASYNC16(base + A_BYTES + r * (LDS_K * 4) + c * 16, b0 + (size_t)r * GK + c * 4);
        }
    };

    load_stage(0, 0); CP_COMMIT();
    load_stage(1, 1); CP_COMMIT();

    float acc[4][8][4];
    #pragma unroll
    for (int mt = 0; mt < 4; mt++)
        #pragma unroll
        for (int nt = 0; nt < 8; nt++)
            #pragma unroll
            for (int i = 0; i < 4; i++) acc[mt][nt][i] = 0.f;

    const int NSTAGE = GK / 32;   // 16
    #pragma unroll 1
    for (int s = 0; s < NSTAGE; s++) {
        if (s + 1 < NSTAGE) { CP_WAIT1(); } else { CP_WAIT0(); }
        __syncthreads();   // the ONLY barrier per stage

        // issue next loads first — overlap L2 latency with the MMA burst
        if (s + 2 < NSTAGE) { load_stage(s + 2, (s + 2) % 3); CP_COMMIT(); }

        const int buf = s % 3;
        const float* As = (const float*)(smem + buf * STAGE_BYTES);
        const float* Bs = (const float*)(smem + buf * STAGE_BYTES + A_BYTES);
        const int arow = wm * 64 + l4;
        const int brow = wn * 64 + l4;

        #pragma unroll
        for (int kk = 0; kk < 4; kk++) {
            int kA = kk * 8 + lc;
            uint32_t a[4][4], b[8][2];
            #pragma unroll
            for (int mt = 0; mt < 4; mt++) {
                const float* p = As + (arow + mt * 16) * LDS_K + kA;
                a[mt][0] = __float_as_uint(p[0]);
                a[mt][1] = __float_as_uint(p[8 * LDS_K]);
                a[mt][2] = __float_as_uint(p[4]);
                a[mt][3] = __float_as_uint(p[8 * LDS_K + 4]);
            }
            #pragma unroll
            for (int nt = 0; nt < 8; nt++) {
                const float* p = Bs + (brow + nt * 8) * LDS_K + kA;
                b[nt][0] = __float_as_uint(p[0]);
                b[nt][1] = __float_as_uint(p[4]);
            }
            #pragma unroll
            for (int mt = 0; mt < 4; mt++)
                #pragma unroll
                for (int nt = 0; nt < 8; nt++)
                    MMA_TF32(acc[mt][nt], a[mt], b[nt]);
        }
    }

    #pragma unroll
    for (int mt = 0; mt < 4; mt++) {
        int r0 = m0 + wm * 64 + mt * 16 + l4;
        #pragma unroll
        for (int nt = 0; nt < 8; nt++) {
            int c0 = n0 + wn * 64 + nt * 8 + 2 * lc;
            float bv0 = bias[c0], bv1 = bias[c0 + 1];
            float v0 = acc[mt][nt][0] + bv0;
            float v1 = acc[mt][nt][1] + bv1;
            float v2 = acc[mt][nt][2] + bv0;
            float v3 = acc[mt][nt][3] + bv1;
            if (SILU) {
                v0 = __fdividef(v0, 1.f + __expf(-v0));
                v1 = __fdividef(v1, 1.f + __expf(-v1));
                v2 = __fdividef(v2, 1.f + __expf(-v2));
                v3 = __fdividef(v3, 1.f + __expf(-v3));
            }
            *(float2*)(C + (size_t)r0 * ldc + c0) = make_float2(v0, v1);
            *(float2*)(C + (size_t)(r0 + 8) * ldc + c0) = make_float2(v2, v3);
        }
    }
}

// ---------------------------------------------------------------------------
// Tensor-core attention (128 threads, 4 warps) with precomputed bias.
// S-phase: warp w covers keys [w*16, w*16+16). PV: d-cols [w*16, w*16+16).
// ---------------------------------------------------------------------------
#define PQK 68
#define PV2 72
#define PS  72
#define ATTN_SMEM ((64 * PQK * 2 + 64 * PV2 + 64 * PS) * 4)

__global__ __launch_bounds__(128) void attn_tc_kernel(
    const float* __restrict__ act,
    const float* __restrict__ bias,
    float* __restrict__ attn_out)
{
    extern __shared__ float sm[];
    float* Qs = sm;                     // 64 x 68
    float* Ks = Qs + 64 * PQK;          // 64 x 68
    float* Vs = Ks + 64 * PQK;          // 64 x 72 ([key][d])
    float* Ss = Vs + 64 * PV2;          // 64 x 72 (bias in / weights out)
    const uint32_t ss_base = smem_u32(Ss);

    const int tid = threadIdx.x;
    const int lane = tid & 31;
    const int w = tid >> 5;
    const int l4 = lane >> 2;
    const int lc = lane & 3;
    const int qt = 15 - blockIdx.x;     // heavy tiles first
    const int bh = blockIdx.y;
    const int b = bh >> 3, h = bh & 7;
    const int q0 = qt * 64;

    const float* actb = act + (size_t)b * NN * 2048;

    // Q tile: prescale by 0.125 (exact), round to tf32
    for (int i = tid; i < 64 * 16; i += 128) {
        int r = i >> 4, c4 = (i & 15) * 4;
        float4 v = *(const float4*)(actb + (size_t)(q0 + r) * 2048 + 512 + h * 64 + c4);
        Qs[r * PQK + c4 + 0] = to_tf32(v.x * 0.125f);
        Qs[r * PQK + c4 + 1] = to_tf32(v.y * 0.125f);
        Qs[r * PQK + c4 + 2] = to_tf32(v.z * 0.125f);
        Qs[r * PQK + c4 + 3] = to_tf32(v.w * 0.125f);
    }

    float acc[4][2][4];
    #pragma unroll
    for (int mt = 0; mt < 4; mt++)
        #pragma unroll
        for (int nt = 0; nt < 2; nt++)
            #pragma unroll
            for (int j = 0; j < 4; j++) acc[mt][nt][j] = 0.f;

    #pragma unroll 1
    for (int kt = 0; kt <= qt; kt++) {
        const int k0 = kt * 64;
        __syncthreads();   // prev-iter readers of Ss/Ks/Vs done

        // bias tile -> Ss via cp.async (overlaps with K/V LDG below)
        const float* bsrc = bias + ((size_t)(b * NN + q0)) * NN + k0;
        #pragma unroll
        for (int q8 = 0; q8 < 8; q8++) {
            int idx = q8 * 128 + tid;
            int r = idx >> 4, c = idx & 15;
            CP_ASYNC16(ss_base + (r * PS + c * 4) * 4, bsrc + (size_t)r * NN + c * 4);
        }
        CP_COMMIT();

        // K / V tiles (tf32-rounded)
        for (int i = tid; i < 64 * 16; i += 128) {
            int r = i >> 4, c4 = (i & 15) * 4;
            float4 kv = *(const float4*)(actb + (size_t)(k0 + r) * 2048 + 1024 + h * 64 + c4);
            Ks[r * PQK + c4 + 0] = to_tf32(kv.x);
            Ks[r * PQK + c4 + 1] = to_tf32(kv.y);
            Ks[r * PQK + c4 + 2] = to_tf32(kv.z);
            Ks[r * PQK + c4 + 3] = to_tf32(kv.w);
            float4 vv = *(const float4*)(actb + (size_t)(k0 + r) * 2048 + 1536 + h * 64 + c4);
            Vs[r * PV2 + c4 + 0] = to_tf32(vv.x);
            Vs[r * PV2 + c4 + 1] = to_tf32(vv.y);
            Vs[r * PV2 + c4 + 2] = to_tf32(vv.z);
            Vs[r * PV2 + c4 + 3] = to_tf32(vv.w);
        }
        CP_WAIT0();
        __syncthreads();

        // --- S = (Q*scale) K^T (warp w covers keys [w*16, w*16+16)) ---
        float sacc[4][2][4];
        #pragma unroll
        for (int mt = 0; mt < 4; mt++)
            #pragma unroll
            for (int nt = 0; nt < 2; nt++)
                #pragma unroll
                for (int j = 0; j < 4; j++) sacc[mt][nt][j] = 0.f;

        #pragma unroll
        for (int ks = 0; ks < 8; ks++) {
            int kA = ks * 8 + lc;
            uint32_t a[4][4], bb[2][2];
            #pragma unroll
            for (int mt = 0; mt < 4; mt++) {
                const float* p = Qs + (mt * 16 + l4) * PQK + kA;
                a[mt][0] = __float_as_uint(p[0]);
                a[mt][1] = __float_as_uint(p[8 * PQK]);
                a[mt][2] = __float_as_uint(p[4]);
                a[mt][3] = __float_as_uint(p[8 * PQK + 4]);
            }
            #pragma unroll
            for (int nt = 0; nt < 2; nt++) {
                const float* p = Ks + (w * 16 + nt * 8 + l4) * PQK + kA;
                bb[nt][0] = __float_as_uint(p[0]);
                bb[nt][1] = __float_as_uint(p[4]);
            }
            #pragma unroll
            for (int mt = 0; mt < 4; mt++)
                #pragma unroll
                for (int nt = 0; nt < 2; nt++)
                    MMA_TF32(sacc[mt][nt], a[mt], bb[nt]);
        }

        // --- epilogue: score + bias -> silu -> mask; RMW Ss in-place ---
        const bool diag = (kt == qt);
        #pragma unroll
        for (int mt = 0; mt < 4; mt++) {
            #pragma unroll
            for (int nt = 0; nt < 2; nt++) {
                int kl = w * 16 + nt * 8 + 2 * lc;
                #pragma unroll
                for (int half = 0; half < 2; half++) {
                    int ql = mt * 16 + l4 + half * 8;
                    float2 bv = *(const float2*)&Ss[ql * PS + kl];
                    float sc0 = sacc[mt][nt][half * 2 + 0] + bv.x;
                    float sc1 = sacc[mt][nt][half * 2 + 1] + bv.y;
                    float v0 = __fdividef(sc0, 1.f + __expf(-sc0));
                    float v1 = __fdividef(sc1, 1.f + __expf(-sc1));
                    if (diag) {
                        if (kl > ql) v0 = 0.f;
                        if (kl + 1 > ql) v1 = 0.f;
                    }
                    float2 o; o.x = to_tf32(v0); o.y = to_tf32(v1);
                    *(float2*)&Ss[ql * PS + kl] = o;
                }
            }
        }
        __syncthreads();

        // --- PV: acc += S @ V (warp w covers d-cols [w*16, w*16+16)) ---
        #pragma unroll
        for (int ks = 0; ks < 8; ks++) {
            int kA = ks * 8 + lc;
            uint32_t a[4][4], bb[2][2];
            #pragma unroll
            for (int mt = 0; mt < 4; mt++) {
                const float* p = Ss + (mt * 16 + l4) * PS + kA;
                a[mt][0] = __float_as_uint(p[0]);
                a[mt][1] = __float_as_uint(p[8 * PS]);
                a[mt][2] = __float_as_uint(p[4]);
                a[mt][3] = __float_as_uint(p[8 * PS + 4]);
            }
            #pragma unroll
            for (int nt = 0; nt < 2; nt++) {
                const float* p = Vs + (ks * 8 + lc) * PV2 + w * 16 + nt * 8 + l4;
                bb[nt][0] = __float_as_uint(p[0]);
                bb[nt][1] = __float_as_uint(p[4 * PV2]);
            }
            #pragma unroll
            for (int mt = 0; mt < 4; mt++)
                #pragma unroll
                for (int nt = 0; nt < 2; nt++)
                    MMA_TF32(acc[mt][nt], a[mt], bb[nt]);
        }
    }

    // --- output: gate by U, round to tf32 for GEMM2 ---
    #pragma unroll
    for (int mt = 0; mt < 4; mt++) {
        #pragma unroll
        for (int half = 0; half < 2; half++) {
            int q = q0 + mt * 16 + l4 + half * 8;
            #pragma unroll
            for (int nt = 0; nt < 2; nt++) {
                int d = w * 16 + nt * 8 + 2 * lc;
                float2 uv = *(const float2*)(actb + (size_t)q * 2048 + h * 64 + d);
                float2 o;
                o.x = to_tf32(acc[mt][nt][half * 2 + 0] * uv.x);
                o.y = to_tf32(acc[mt][nt][half * 2 + 1] * uv.y);
                *(float2*)(attn_out + ((size_t)b * NN + q) * HH + h * 64 + d) = o;
            }
        }
    }
}

// ---------------------------------------------------------------------------
extern "C" void kernel_launch(void* const* d_in, const int* in_sizes, int n_in,
                              void* d_out, int out_size) {
    const float* x     = (const float*)d_in[0];
    const int*   tsi   = (const int*)  d_in[1];
    const float* f1_w  = (const float*)d_in[3];
    const float* f1_b  = (const float*)d_in[4];
    const float* f2_w  = (const float*)d_in[5];
    const float* f2_b  = (const float*)d_in[6];
    const float* ts_w  = (const float*)d_in[7];
    const float* pos_w = (const float*)d_in[8];
    float* out = (float*)d_out;

    float *actp, *attnp, *tsp, *xrp, *w1p, *w2p, *biasp;
    cudaGetSymbolAddress((void**)&actp, g_act);
    cudaGetSymbolAddress((void**)&attnp, g_attn);
    cudaGetSymbolAddress((void**)&tsp, g_ts);
    cudaGetSymbolAddress((void**)&xrp, g_xr);
    cudaGetSymbolAddress((void**)&w1p, g_w1r);
    cudaGetSymbolAddress((void**)&w2p, g_w2r);
    cudaGetSymbolAddress((void**)&biasp, g_bias);

    cudaFuncSetAttribute(gemm_mma_kernel<true>,
                         cudaFuncAttributeMaxDynamicSharedMemorySize, GEMM_SMEM);
    cudaFuncSetAttribute(gemm_mma_kernel<false>,
                         cudaFuncAttributeMaxDynamicSharedMemorySize, GEMM_SMEM);
    cudaFuncSetAttribute(attn_tc_kernel,
                         cudaFuncAttributeMaxDynamicSharedMemorySize, ATTN_SMEM);

    // Launch order keeps GEMM1 at index 3 (the slot ncu samples).
    ts_convert_kernel<<<32, 256>>>(tsi, tsp);                                     // 0
    round_tf32_kernel<<<(BB * NN * HH + 255) / 256, 256>>>(x, xrp, BB * NN * HH); // 1
    round_tf32_kernel<<<(4 * HH * HH + 255) / 256, 256>>>(f1_w, w1p, 4 * HH * HH);// 2

    // 3: GEMM1 + SiLU (profiled slot): [8192,512] @ [2048,512]^T
    gemm_mma_kernel<true><<<dim3(16, 64), 128, GEMM_SMEM>>>(xrp, w1p, f1_b, actp, 4 * HH);

    round_tf32_kernel<<<(HH * HH + 255) / 256, 256>>>(f2_w, w2p, HH * HH);        // 4
    bias_kernel<<<dim3(136, BB), 256>>>(tsp, ts_w, pos_w, biasp);                 // 5

    // 6: tensor-core attention (+ fused U gating, tf32 round)
    attn_tc_kernel<<<dim3(16, 64), 128, ATTN_SMEM>>>(actp, biasp, attnp);

    // 7: GEMM2: gated @ [512,512]^T + f2_b -> out
    gemm_mma_kernel<false><<<dim3(4, 64), 128, GEMM_SMEM>>>(attnp, w2p, f2_b, out, HH);
}

// round 16
// speedup vs baseline: 1.0758x; 1.0714x over previous
#include <cuda_runtime.h>
#include <cstdint>

#define BB 8
#define NN 1024
#define HH 512

// Scratch (allocation-free rule: __device__ globals)
__device__ float g_act[(size_t)BB * NN * 4 * HH];   // 8192 x 2048 : [U | Q | K | V], tf32 values
__device__ float g_attn[(size_t)BB * NN * HH];      // 8192 x 512 (gated, tf32-rounded)
__device__ float g_xr[(size_t)BB * NN * HH];        // x rounded to tf32
__device__ float g_w1r[(size_t)4 * HH * HH];        // f1_w rounded to tf32
__device__ float g_w2r[(size_t)HH * HH];            // f2_w rounded to tf32
__device__ float g_bias[(size_t)BB * NN * NN];      // rel-attn bias (head-independent)

// ---------------------------------------------------------------------------
__device__ __forceinline__ uint32_t smem_u32(const void* p) {
    uint32_t a;
    asm("{ .reg .u64 t; cvta.to.shared.u64 t, %1; cvt.u32.u64 %0, t; }" : "=r"(a) : "l"(p));
    return a;
}
__device__ __forceinline__ float to_tf32(float x) {
    float r; asm("cvt.rna.tf32.f32 %0, %1;" : "=f"(r) : "f"(x)); return r;
}

#define CP_ASYNC16(dst, src) \
    asm volatile("cp.async.cg.shared.global [%0], [%1], 16;" :: "r"(dst), "l"(src) : "memory")
#define CP_COMMIT() asm volatile("cp.async.commit_group;" ::: "memory")
#define CP_WAIT1()  asm volatile("cp.async.wait_group 1;" ::: "memory")
#define CP_WAIT0()  asm volatile("cp.async.wait_group 0;" ::: "memory")

#define MMA_TF32(c, a, b)                                                        \
    asm volatile("mma.sync.aligned.m16n8k8.row.col.f32.tf32.tf32.f32 "           \
        "{%0,%1,%2,%3}, {%4,%5,%6,%7}, {%8,%9}, {%0,%1,%2,%3};"                  \
        : "+f"((c)[0]), "+f"((c)[1]), "+f"((c)[2]), "+f"((c)[3])                  \
        : "r"((a)[0]), "r"((a)[1]), "r"((a)[2]), "r"((a)[3]),                     \
          "r"((b)[0]), "r"((b)[1]))

// ---------------------------------------------------------------------------
// Prep: single fused tf32 rounding kernel (x, f1_w, f2_w)
// ---------------------------------------------------------------------------
#define NX  (BB * NN * HH)
#define NW1 (4 * HH * HH)
#define NW2 (HH * HH)

__global__ void round_all_kernel(const float* __restrict__ x,
                                 const float* __restrict__ w1,
                                 const float* __restrict__ w2,
                                 float* __restrict__ xr,
                                 float* __restrict__ w1r,
                                 float* __restrict__ w2r)
{
    int i = blockIdx.x * 256 + threadIdx.x;
    if (i < NX) { xr[i] = to_tf32(x[i]); return; }
    int j = i - NX;
    if (j < NW1) { w1r[j] = to_tf32(w1[j]); return; }
    int k = j - NW1;
    if (k < NW2) w2r[k] = to_tf32(w2[k]);
}

// Precompute bias[b][q][k] = pos_w[N-1+k-q] + ts_w[bucket(|ts_ext[q+1]-ts[k]|)]
// ts conversion (int32/int64 -> fp32 seconds) folded in.
__global__ __launch_bounds__(256) void bias_kernel(
    const int* __restrict__ t, const float* __restrict__ ts_w,
    const float* __restrict__ pos_w, float* __restrict__ bias)
{
    __shared__ float tq_s[64], tk_s[64];
    int b = blockIdx.y;
    int idx = blockIdx.x;
    int qt = (int)((sqrtf(8.f * idx + 1.f) - 1.f) * 0.5f);
    while ((qt + 1) * (qt + 2) / 2 <= idx) qt++;
    while (qt * (qt + 1) / 2 > idx) qt--;
    int kt = idx - qt * (qt + 1) / 2;
    int q0 = qt * 64, k0 = kt * 64;
    int tid = threadIdx.x;

    bool is64 = (t[1] == 0 && t[3] == 0 && t[5] == 0 && t[7] == 0);
    if (tid < 64) {
        int qq = min(q0 + tid + 1, NN - 1);
        long long v = is64 ? ((const long long*)t)[b * NN + qq] : (long long)t[b * NN + qq];
        tq_s[tid] = (float)v / 1e9f;
    } else if (tid < 128) {
        int kk = k0 + tid - 64;
        long long v = is64 ? ((const long long*)t)[b * NN + kk] : (long long)t[b * NN + kk];
        tk_s[tid - 64] = (float)v / 1e9f;
    }
    __syncthreads();

    #pragma unroll
    for (int it = 0; it < 4; it++) {
        int r = (tid >> 4) + it * 16;
        int c = (tid & 15) * 4;
        int q = q0 + r;
        float tq = tq_s[r];
        float4 o;
        #pragma unroll
        for (int j = 0; j < 4; j++) {
            int k = k0 + c + j;
            float ad = fmaxf(fabsf(tq - tk_s[c + j]), 1.0f);
            int bucket = (int)floorf(__logf(ad) * 3.3222591f);
            bucket = bucket < 0 ? 0 : (bucket > 64 ? 64 : bucket);
            ((float*)&o)[j] = pos_w[NN - 1 + k - q] + ts_w[bucket];
        }
        *(float4*)(bias + ((size_t)(b * NN + q)) * NN + k0 + c) = o;
    }
}

// ---------------------------------------------------------------------------
// mma.sync tf32 GEMM: C = A*W^T + bias (opt SiLU; SILU also rounds output
// to tf32 so downstream attention can consume it directly as MMA input).
// CTA 128x128, 128 threads (4 warps 2x2), warp tile 64x64, 2 CTAs/SM,
// double-buffered cp.async (best-measured R10 config).
// ---------------------------------------------------------------------------
#define GK 512
#define LDS_K 36
#define A_BYTES (128 * LDS_K * 4)
#define B_BYTES (128 * LDS_K * 4)
#define STAGE_BYTES (A_BYTES + B_BYTES)       // 36864
#define GEMM_SMEM (2 * STAGE_BYTES)           // 73728

template<bool SILU>
__global__ __launch_bounds__(128, 2) void gemm_mma_kernel(
    const float* __restrict__ A, const float* __restrict__ W,
    const float* __restrict__ bias, float* __restrict__ C, int ldc)
{
    extern __shared__ char smem[];
    const uint32_t sb = smem_u32(smem);
    const int tid = threadIdx.x;
    const int lane = tid & 31;
    const int wid = tid >> 5;
    const int wm = wid >> 1;
    const int wn = wid & 1;
    const int l4 = lane >> 2;
    const int lc = lane & 3;
    const int m0 = blockIdx.y * 128;
    const int n0 = blockIdx.x * 128;

    auto load_stage = [&](int s, int buf) {
        uint32_t base = sb + buf * STAGE_BYTES;
        const float* a0 = A + (size_t)m0 * GK + s * 32;
        #pragma unroll
        for (int q = 0; q < 8; q++) {
            int idx = q * 128 + tid;
            int r = idx >> 3, c = idx & 7;
            CP_ASYNC16(base + r * (LDS_K * 4) + c * 16, a0 + (size_t)r * GK + c * 4);
        }
        const float* b0 = W + (size_t)n0 * GK + s * 32;
        #pragma unroll
        for (int q = 0; q < 8; q++) {
            int idx = q * 128 + tid;
            int r = idx >> 3, c = idx & 7;
            CP_ASYNC16(base + A_BYTES + r * (LDS_K * 4) + c * 16, b0 + (size_t)r * GK + c * 4);
        }
    };

    load_stage(0, 0); CP_COMMIT();
    load_stage(1, 1); CP_COMMIT();

    float acc[4][8][4];
    #pragma unroll
    for (int mt = 0; mt < 4; mt++)
        #pragma unroll
        for (int nt = 0; nt < 8; nt++)
            #pragma unroll
            for (int i = 0; i < 4; i++) acc[mt][nt][i] = 0.f;

    const int NSTAGE = GK / 32;
    #pragma unroll 1
    for (int s = 0; s < NSTAGE; s++) {
        if (s == NSTAGE - 1) { CP_WAIT0(); } else { CP_WAIT1(); }
        __syncthreads();

        const float* As = (const float*)(smem + (s & 1) * STAGE_BYTES);
        const float* Bs = (const float*)(smem + (s & 1) * STAGE_BYTES + A_BYTES);
        const int arow = wm * 64 + l4;
        const int brow = wn * 64 + l4;

        #pragma unroll
        for (int kk = 0; kk < 4; kk++) {
            int kA = kk * 8 + lc;
            uint32_t a[4][4], b[8][2];
            #pragma unroll
            for (int mt = 0; mt < 4; mt++) {
                const float* p = As + (arow + mt * 16) * LDS_K + kA;
                a[mt][0] = __float_as_uint(p[0]);
                a[mt][1] = __float_as_uint(p[8 * LDS_K]);
                a[mt][2] = __float_as_uint(p[4]);
                a[mt][3] = __float_as_uint(p[8 * LDS_K + 4]);
            }
            #pragma unroll
            for (int nt = 0; nt < 8; nt++) {
                const float* p = Bs + (brow + nt * 8) * LDS_K + kA;
                b[nt][0] = __float_as_uint(p[0]);
                b[nt][1] = __float_as_uint(p[4]);
            }
            #pragma unroll
            for (int mt = 0; mt < 4; mt++)
                #pragma unroll
                for (int nt = 0; nt < 8; nt++)
                    MMA_TF32(acc[mt][nt], a[mt], b[nt]);
        }

        __syncthreads();
        if (s + 2 < NSTAGE) { load_stage(s + 2, s & 1); CP_COMMIT(); }
    }

    #pragma unroll
    for (int mt = 0; mt < 4; mt++) {
        int r0 = m0 + wm * 64 + mt * 16 + l4;
        #pragma unroll
        for (int nt = 0; nt < 8; nt++) {
            int c0 = n0 + wn * 64 + nt * 8 + 2 * lc;
            float bv0 = bias[c0], bv1 = bias[c0 + 1];
            float v0 = acc[mt][nt][0] + bv0;
            float v1 = acc[mt][nt][1] + bv1;
            float v2 = acc[mt][nt][2] + bv0;
            float v3 = acc[mt][nt][3] + bv1;
            if (SILU) {
                v0 = to_tf32(__fdividef(v0, 1.f + __expf(-v0)));
                v1 = to_tf32(__fdividef(v1, 1.f + __expf(-v1)));
                v2 = to_tf32(__fdividef(v2, 1.f + __expf(-v2)));
                v3 = to_tf32(__fdividef(v3, 1.f + __expf(-v3)));
            }
            *(float2*)(C + (size_t)r0 * ldc + c0) = make_float2(v0, v1);
            *(float2*)(C + (size_t)(r0 + 8) * ldc + c0) = make_float2(v2, v3);
        }
    }
}

// ---------------------------------------------------------------------------
// Tensor-core attention (128 threads, 4 warps). act holds tf32 values, so
// Q/K/V tiles stream in via cp.async (no LDG->cvt->STS). Two commit groups
// per k-iter: K alone (waited before S-phase), V+bias (waited after S MMAs,
// hiding their latency behind tensor work). Scale 0.125 fused into epilogue.
// ---------------------------------------------------------------------------
#define PQK 68
#define PV2 72
#define PS  72
#define ATTN_SMEM ((64 * PQK * 2 + 64 * PV2 + 64 * PS) * 4)

__global__ __launch_bounds__(128) void attn_tc_kernel(
    const float* __restrict__ act,
    const float* __restrict__ bias,
    float* __restrict__ attn_out)
{
    extern __shared__ float sm[];
    float* Qs = sm;                     // 64 x 68
    float* Ks = Qs + 64 * PQK;          // 64 x 68
    float* Vs = Ks + 64 * PQK;          // 64 x 72 ([key][d])
    float* Ss = Vs + 64 * PV2;          // 64 x 72 (bias in / weights out)
    const uint32_t qs_base = smem_u32(Qs);
    const uint32_t ks_base = smem_u32(Ks);
    const uint32_t vs_base = smem_u32(Vs);
    const uint32_t ss_base = smem_u32(Ss);

    const int tid = threadIdx.x;
    const int lane = tid & 31;
    const int w = tid >> 5;
    const int l4 = lane >> 2;
    const int lc = lane & 3;
    const int qt = 15 - blockIdx.x;     // heavy tiles first
    const int bh = blockIdx.y;
    const int b = bh >> 3, h = bh & 7;
    const int q0 = qt * 64;

    const float* actb = act + (size_t)b * NN * 2048;

    // Q tile via cp.async (group 0; drained by the first iter's CP_WAIT1)
    {
        const float* qsrc = actb + (size_t)q0 * 2048 + 512 + h * 64;
        #pragma unroll
        for (int q8 = 0; q8 < 8; q8++) {
            int idx = q8 * 128 + tid;
            int r = idx >> 4, c = idx & 15;
            CP_ASYNC16(qs_base + (r * PQK + c * 4) * 4, qsrc + (size_t)r * 2048 + c * 4);
        }
        CP_COMMIT();
    }

    float acc[4][2][4];
    #pragma unroll
    for (int mt = 0; mt < 4; mt++)
        #pragma unroll
        for (int nt = 0; nt < 2; nt++)
            #pragma unroll
            for (int j = 0; j < 4; j++) acc[mt][nt][j] = 0.f;

    #pragma unroll 1
    for (int kt = 0; kt <= qt; kt++) {
        const int k0 = kt * 64;
        __syncthreads();   // prev-iter readers of Ks/Vs/Ss done

        // group: K tile
        const float* ksrc = actb + (size_t)k0 * 2048 + 1024 + h * 64;
        #pragma unroll
        for (int q8 = 0; q8 < 8; q8++) {
            int idx = q8 * 128 + tid;
            int r = idx >> 4, c = idx & 15;
            CP_ASYNC16(ks_base + (r * PQK + c * 4) * 4, ksrc + (size_t)r * 2048 + c * 4);
        }
        CP_COMMIT();

        // group: V tile + bias tile (latency hidden behind S-phase MMAs)
        const float* vsrc = actb + (size_t)k0 * 2048 + 1536 + h * 64;
        const float* bsrc = bias + ((size_t)(b * NN + q0)) * NN + k0;
        #pragma unroll
        for (int q8 = 0; q8 < 8; q8++) {
            int idx = q8 * 128 + tid;
            int r = idx >> 4, c = idx & 15;
            CP_ASYNC16(vs_base + (r * PV2 + c * 4) * 4, vsrc + (size_t)r * 2048 + c * 4);
            CP_ASYNC16(ss_base + (r * PS + c * 4) * 4, bsrc + (size_t)r * NN + c * 4);
        }
        CP_COMMIT();

        CP_WAIT1();        // K (and Q on first iter) arrived; V+bias may pend
        __syncthreads();

        // --- S = Q K^T (warp w covers keys [w*16, w*16+16)) ---
        float sacc[4][2][4];
        #pragma unroll
        for (int mt = 0; mt < 4; mt++)
            #pragma unroll
            for (int nt = 0; nt < 2; nt++)
                #pragma unroll
                for (int j = 0; j < 4; j++) sacc[mt][nt][j] = 0.f;

        #pragma unroll
        for (int ks = 0; ks < 8; ks++) {
            int kA = ks * 8 + lc;
            uint32_t a[4][4], bb[2][2];
            #pragma unroll
            for (int mt = 0; mt < 4; mt++) {
                const float* p = Qs + (mt * 16 + l4) * PQK + kA;
                a[mt][0] = __float_as_uint(p[0]);
                a[mt][1] = __float_as_uint(p[8 * PQK]);
                a[mt][2] = __float_as_uint(p[4]);
                a[mt][3] = __float_as_uint(p[8 * PQK + 4]);
            }
            #pragma unroll
            for (int nt = 0; nt < 2; nt++) {
                const float* p = Ks + (w * 16 + nt * 8 + l4) * PQK + kA;
                bb[nt][0] = __float_as_uint(p[0]);
                bb[nt][1] = __float_as_uint(p[4]);
            }
            #pragma unroll
            for (int mt = 0; mt < 4; mt++)
                #pragma unroll
                for (int nt = 0; nt < 2; nt++)
                    MMA_TF32(sacc[mt][nt], a[mt], bb[nt]);
        }

        CP_WAIT0();        // V + bias arrived
        __syncthreads();

        // --- epilogue: 0.125*score + bias -> silu -> mask; RMW Ss in-place ---
        const bool diag = (kt == qt);
        #pragma unroll
        for (int mt = 0; mt < 4; mt++) {
            #pragma unroll
            for (int nt = 0; nt < 2; nt++) {
                int kl = w * 16 + nt * 8 + 2 * lc;
                #pragma unroll
                for (int half = 0; half < 2; half++) {
                    int ql = mt * 16 + l4 + half * 8;
                    float2 bv = *(const float2*)&Ss[ql * PS + kl];
                    float sc0 = fmaf(sacc[mt][nt][half * 2 + 0], 0.125f, bv.x);
                    float sc1 = fmaf(sacc[mt][nt][half * 2 + 1], 0.125f, bv.y);
                    float v0 = __fdividef(sc0, 1.f + __expf(-sc0));
                    float v1 = __fdividef(sc1, 1.f + __expf(-sc1));
                    if (diag) {
                        if (kl > ql) v0 = 0.f;
                        if (kl + 1 > ql) v1 = 0.f;
                    }
                    float2 o; o.x = to_tf32(v0); o.y = to_tf32(v1);
                    *(float2*)&Ss[ql * PS + kl] = o;
                }
            }
        }
        __syncthreads();

        // --- PV: acc += S @ V (warp w covers d-cols [w*16, w*16+16)) ---
        #pragma unroll
        for (int ks = 0; ks < 8; ks++) {
            int kA = ks * 8 + lc;
            uint32_t a[4][4], bb[2][2];
            #pragma unroll
            for (int mt = 0; mt < 4; mt++) {
                const float* p = Ss + (mt * 16 + l4) * PS + kA;
                a[mt][0] = __float_as_uint(p[0]);
                a[mt][1] = __float_as_uint(p[8 * PS]);
                a[mt][2] = __float_as_uint(p[4]);
                a[mt][3] = __float_as_uint(p[8 * PS + 4]);
            }
            #pragma unroll
            for (int nt = 0; nt < 2; nt++) {
                const float* p = Vs + (ks * 8 + lc) * PV2 + w * 16 + nt * 8 + l4;
                bb[nt][0] = __float_as_uint(p[0]);
                bb[nt][1] = __float_as_uint(p[4 * PV2]);
            }
            #pragma unroll
            for (int mt = 0; mt < 4; mt++)
                #pragma unroll
                for (int nt = 0; nt < 2; nt++)
                    MMA_TF32(acc[mt][nt], a[mt], bb[nt]);
        }
    }

    // --- output: gate by U (tf32 values), round to tf32 for GEMM2 ---
    #pragma unroll
    for (int mt = 0; mt < 4; mt++) {
        #pragma unroll
        for (int half = 0; half < 2; half++) {
            int q = q0 + mt * 16 + l4 + half * 8;
            #pragma unroll
            for (int nt = 0; nt < 2; nt++) {
                int d = w * 16 + nt * 8 + 2 * lc;
                float2 uv = *(const float2*)(actb + (size_t)q * 2048 + h * 64 + d);
                float2 o;
                o.x = to_tf32(acc[mt][nt][half * 2 + 0] * uv.x);
                o.y = to_tf32(acc[mt][nt][half * 2 + 1] * uv.y);
                *(float2*)(attn_out + ((size_t)b * NN + q) * HH + h * 64 + d) = o;
            }
        }
    }
}

// ---------------------------------------------------------------------------
extern "C" void kernel_launch(void* const* d_in, const int* in_sizes, int n_in,
                              void* d_out, int out_size) {
    const float* x     = (const float*)d_in[0];
    const int*   tsi   = (const int*)  d_in[1];
    const float* f1_w  = (const float*)d_in[3];
    const float* f1_b  = (const float*)d_in[4];
    const float* f2_w  = (const float*)d_in[5];
    const float* f2_b  = (const float*)d_in[6];
    const float* ts_w  = (const float*)d_in[7];
    const float* pos_w = (const float*)d_in[8];
    float* out = (float*)d_out;

    float *actp, *attnp, *xrp, *w1p, *w2p, *biasp;
    cudaGetSymbolAddress((void**)&actp, g_act);
    cudaGetSymbolAddress((void**)&attnp, g_attn);
    cudaGetSymbolAddress((void**)&xrp, g_xr);
    cudaGetSymbolAddress((void**)&w1p, g_w1r);
    cudaGetSymbolAddress((void**)&w2p, g_w2r);
    cudaGetSymbolAddress((void**)&biasp, g_bias);

    cudaFuncSetAttribute(gemm_mma_kernel<true>,
                         cudaFuncAttributeMaxDynamicSharedMemorySize, GEMM_SMEM);
    cudaFuncSetAttribute(gemm_mma_kernel<false>,
                         cudaFuncAttributeMaxDynamicSharedMemorySize, GEMM_SMEM);
    cudaFuncSetAttribute(attn_tc_kernel,
                         cudaFuncAttributeMaxDynamicSharedMemorySize, ATTN_SMEM);

    // 0: fused tf32 rounding of x, f1_w, f2_w
    round_all_kernel<<<(NX + NW1 + NW2 + 255) / 256, 256>>>(x, f1_w, f2_w, xrp, w1p, w2p);

    // 1: bias precompute (ts conversion inline)
    bias_kernel<<<dim3(136, BB), 256>>>(tsi, ts_w, pos_w, biasp);

    // 2: GEMM1 + SiLU (+tf32 round): [8192,512] @ [2048,512]^T -> g_act
    gemm_mma_kernel<true><<<dim3(16, 64), 128, GEMM_SMEM>>>(xrp, w1p, f1_b, actp, 4 * HH);

    // 3: tensor-core attention (PROFILED SLOT)
    attn_tc_kernel<<<dim3(16, 64), 128, ATTN_SMEM>>>(actp, biasp, attnp);

    // 4: GEMM2: gated @ [512,512]^T + f2_b -> out
    gemm_mma_kernel<false><<<dim3(4, 64), 128, GEMM_SMEM>>>(attnp, w2p, f2_b, out, HH);
}